// round 12
// baseline (speedup 1.0000x reference)
#include <cuda_runtime.h>
#include <math_constants.h>

#define N_EMBED   64
#define BPS       4
#define NSM       152
#define NBLK      (NSM * BPS)              // 608
#define NTHREADS  128
#define NGROUPS   (NBLK * NTHREADS / 4)    // 19456 four-lane groups

// Per-block likelihood partials [codeword][block] + launch-persistent ticket.
__device__ __align__(16) float g_part[N_EMBED * NBLK];
__device__ unsigned int g_tick;

__device__ __forceinline__ float ex2f(float x) { float r; asm("ex2.approx.f32 %0,%1;" : "=f"(r) : "f"(x)); return r; }
__device__ __forceinline__ float rcpf(float x) { float r; asm("rcp.approx.f32 %0,%1;" : "=f"(r) : "f"(x)); return r; }

__global__ __launch_bounds__(NTHREADS, BPS)
void jsccq_main(const float* __restrict__ x, const float* __restrict__ embed,
                float* __restrict__ out_q, float* __restrict__ out_like,
                int npts, float invN) {
    __shared__ float  s_cx[N_EMBED], s_cy[N_EMBED], s_cz[N_EMBED];
    __shared__ float2 s_emb[N_EMBED];
    __shared__ float  s_like[N_EMBED];
    __shared__ unsigned s_isLast;

    const int tid = threadIdx.x;
    if (tid < N_EMBED) {
        const float s = 10.0f * 1.4426950408889634f;   // sigma * log2(e)
        float ex = embed[2 * tid + 0];
        float ey = embed[2 * tid + 1];
        s_cx[tid]  = 2.0f * s * ex;
        s_cy[tid]  = 2.0f * s * ey;
        s_cz[tid]  = -s * (ex * ex + ey * ey);
        s_emb[tid]  = make_float2(ex, ey);
        s_like[tid] = 0.0f;
    }
    __syncthreads();

    const int lane_in_grp = tid & 3;
    const int base = lane_in_grp * 16;
    const unsigned gmask = 0xFu << ((tid & 31) & ~3);   // 4-lane group mask

    // Register-resident codebook slice (48 regs).
    float cx[16], cy[16], cz[16];
#pragma unroll
    for (int k = 0; k < 16; k++) {
        cx[k] = s_cx[base + k];
        cy[k] = s_cy[base + k];
        cz[k] = s_cz[base + k];
    }

    float acc[16];
#pragma unroll
    for (int k = 0; k < 16; k++) acc[k] = 0.0f;

    const float2* __restrict__ pts = reinterpret_cast<const float2*>(x);
    float2* __restrict__       oq  = reinterpret_cast<float2*>(out_q);

    const int gid   = (blockIdx.x * NTHREADS + tid) >> 2;
    const int iters = (npts + NGROUPS - 1) / NGROUPS;   // uniform trip count

    for (int i = 0; i < iters; i++) {
        const int n = gid + i * NGROUPS;
        const bool act = (n < npts);
        float2 p = act ? pts[n] : make_float2(0.0f, 0.0f);

        // --- logits + max/argmax via 2 interleaved predicated chains ---
        // Argmax tracking rides along with the max chain: no second
        // reduction pass, no extra serial shuffle chain.
        float e[16];
        float m0 = -CUDART_INF_F, m1 = -CUDART_INF_F;
        int   b0 = base, b1 = base + 1;
#pragma unroll
        for (int k = 0; k < 16; k += 2) {
            float l0 = fmaf(p.x, cx[k],     fmaf(p.y, cy[k],     cz[k]));
            float l1 = fmaf(p.x, cx[k + 1], fmaf(p.y, cy[k + 1], cz[k + 1]));
            e[k]     = l0;
            e[k + 1] = l1;
            if (l0 > m0) { m0 = l0; b0 = base + k; }
            if (l1 > m1) { m1 = l1; b1 = base + k + 1; }
        }
        float m  = m0;
        int   bi = b0;
        if (m1 > m0) { m = m1; bi = b1; }

        // cross-lane max/argmax within the 4-lane group (first-occurrence ties)
#pragma unroll
        for (int o = 1; o <= 2; o <<= 1) {
            float om = __shfl_xor_sync(gmask, m,  o);
            int   ob = __shfl_xor_sync(gmask, bi, o);
            if (om > m || (om == m && ob < bi)) { m = om; bi = ob; }
        }

        // --- exps + 4-chain partial sums ---
        float s0 = 0.0f, s1 = 0.0f, s2 = 0.0f, s3 = 0.0f;
#pragma unroll
        for (int k = 0; k < 16; k += 4) {
            float v0 = ex2f(e[k + 0] - m);
            float v1 = ex2f(e[k + 1] - m);
            float v2 = ex2f(e[k + 2] - m);
            float v3 = ex2f(e[k + 3] - m);
            e[k + 0] = v0; e[k + 1] = v1; e[k + 2] = v2; e[k + 3] = v3;
            s0 += v0; s1 += v1; s2 += v2; s3 += v3;
        }
        float ssum = (s0 + s1) + (s2 + s3);
        ssum += __shfl_xor_sync(gmask, ssum, 1);
        ssum += __shfl_xor_sync(gmask, ssum, 2);

        const float inv = act ? rcpf(ssum) : 0.0f;   // inactive -> contributes 0
#pragma unroll
        for (int k = 0; k < 16; k++)
            acc[k] = fmaf(e[k], inv, acc[k]);

        // hard quantize (straight-through forward value = argmax codeword)
        if (act && lane_in_grp == 0)
            oq[n] = s_emb[bi];
    }

    // --- block-level likelihood reduction ---
#pragma unroll
    for (int k = 0; k < 16; k++) {
        float vv = acc[k];
        vv += __shfl_xor_sync(0xffffffffu, vv, 4);
        vv += __shfl_xor_sync(0xffffffffu, vv, 8);
        vv += __shfl_xor_sync(0xffffffffu, vv, 16);
        if ((tid & 31) < 4)
            atomicAdd(&s_like[base + k], vv);
    }
    __syncthreads();
    if (tid < N_EMBED)
        g_part[tid * NBLK + blockIdx.x] = s_like[tid];
    __threadfence();
    __syncthreads();

    // --- last-arriving block reduces partials (replay-safe via mod) ---
    if (tid == 0) {
        unsigned t = atomicAdd(&g_tick, 1u);
        s_isLast = ((t % NBLK) == (NBLK - 1)) ? 1u : 0u;
    }
    __syncthreads();

    if (s_isLast && out_like != nullptr) {
        __threadfence();
        const int cw = tid >> 1;                     // 2 threads per codeword
        const float4* row = reinterpret_cast<const float4*>(&g_part[cw * NBLK])
                          + (tid & 1) * (NBLK / 8);  // 76 float4 each
        float s = 0.0f;
#pragma unroll 4
        for (int i = 0; i < NBLK / 8; i++) {
            float4 q = row[i];
            s += (q.x + q.y) + (q.z + q.w);
        }
        s += __shfl_xor_sync(0xffffffffu, s, 1);
        if ((tid & 1) == 0)
            out_like[cw] = s * invN;
    }
}

extern "C" void kernel_launch(void* const* d_in, const int* in_sizes, int n_in,
                              void* d_out, int out_size) {
    const float* x     = (const float*)d_in[0];   // [64,32,32,32] fp32
    const float* embed = (const float*)d_in[1];   // [64,2]        fp32
    float* out = (float*)d_out;

    const int npts = in_sizes[0] / 2;             // 1,048,576 points

    float* out_like = (out_size >= 2 * npts + N_EMBED) ? (out + 2 * npts) : nullptr;

    jsccq_main<<<NBLK, NTHREADS>>>(x, embed, out, out_like, npts,
                                   1.0f / (float)npts);
}

// round 13
// speedup vs baseline: 1.0029x; 1.0029x over previous
#include <cuda_runtime.h>

#define N_EMBED   64
#define BPS       5
#define NSM       152
#define NBLK      (NSM * BPS)              // 760 blocks of 96 threads
#define NTHREADS  96                       // 3 warps; 15 warps/SM, reg cap 136
#define NGROUPS   (NBLK * NTHREADS / 4)    // 18240 four-lane groups

typedef unsigned long long u64;

// Per-block likelihood partials [codeword][block] + launch-persistent ticket.
__device__ __align__(16) float g_part[N_EMBED * NBLK];
__device__ unsigned int g_tick;

__device__ __forceinline__ float ex2f(float x) { float r; asm("ex2.approx.f32 %0,%1;" : "=f"(r) : "f"(x)); return r; }
__device__ __forceinline__ float rcpf(float x) { float r; asm("rcp.approx.f32 %0,%1;" : "=f"(r) : "f"(x)); return r; }
__device__ __forceinline__ u64  pk2(float lo, float hi) { u64 r; asm("mov.b64 %0,{%1,%2};" : "=l"(r) : "f"(lo), "f"(hi)); return r; }
__device__ __forceinline__ void up2(u64 v, float& lo, float& hi) { asm("mov.b64 {%0,%1},%2;" : "=f"(lo), "=f"(hi) : "l"(v)); }
__device__ __forceinline__ u64  ffma2(u64 a, u64 b, u64 c) { u64 d; asm("fma.rn.f32x2 %0,%1,%2,%3;" : "=l"(d) : "l"(a), "l"(b), "l"(c)); return d; }
__device__ __forceinline__ u64  add2(u64 a, u64 b) { u64 d; asm("add.rn.f32x2 %0,%1,%2;" : "=l"(d) : "l"(a), "l"(b)); return d; }

// One point's full pipeline for this lane's 16 codewords (constants packed).
// EXACT max (FMNMX tree) + EXACT argmax (umin over bits(d)|idx). The shifted
// pair is consumed immediately (encode + EX2) to minimize the live set.
__device__ __forceinline__ void point_body(
    float2 p, int n, int base, int lane_in_grp, unsigned gmask,
    const u64 CX[8], const u64 CY[8], const u64 CZ[8],
    float acc[16], const float2* __restrict__ s_emb,
    float2* __restrict__ oq)
{
    const u64 PX = pk2(p.x, p.x);
    const u64 PY = pk2(p.y, p.y);

    // --- logits (packed FFMA2): l[k] = px*cx + py*cy + cz ---
    u64 L[8];
    float l[16];
#pragma unroll
    for (int i = 0; i < 8; i++) {
        L[i] = ffma2(PX, CX[i], ffma2(PY, CY[i], CZ[i]));
        up2(L[i], l[2 * i], l[2 * i + 1]);
    }

    // --- exact max: FMNMX tree + 2-level cross-lane ---
    float m8[8];
#pragma unroll
    for (int i = 0; i < 8; i++) m8[i] = fmaxf(l[2 * i], l[2 * i + 1]);
    float m4a = fmaxf(m8[0], m8[1]), m4b = fmaxf(m8[2], m8[3]);
    float m4c = fmaxf(m8[4], m8[5]), m4d = fmaxf(m8[6], m8[7]);
    float m   = fmaxf(fmaxf(m4a, m4b), fmaxf(m4c, m4d));
    m = fmaxf(m, __shfl_xor_sync(gmask, m, 1));
    m = fmaxf(m, __shfl_xor_sync(gmask, m, 2));

    // --- fused shift -> (argmax encode, exp) per pair ---
    // d = l - m <= 0, d == +0 exactly at the max; umin over (bits(d)|idx):
    // negatives carry the sign bit and lose; ties pick the smallest index
    // (matches jnp.argmax first-occurrence). Exact.
    const u64 MM = pk2(-m, -m);
    float v[16];
    unsigned e8[8];
#pragma unroll
    for (int i = 0; i < 8; i++) {
        float d0, d1;
        up2(add2(L[i], MM), d0, d1);
        e8[i] = umin(__float_as_uint(d0) | (unsigned)(base + 2 * i),
                     __float_as_uint(d1) | (unsigned)(base + 2 * i + 1));
        v[2 * i]     = ex2f(d0);
        v[2 * i + 1] = ex2f(d1);
    }

    unsigned e4a = umin(e8[0], e8[1]), e4b = umin(e8[2], e8[3]);
    unsigned e4c = umin(e8[4], e8[5]), e4d = umin(e8[6], e8[7]);
    unsigned enc = umin(umin(e4a, e4b), umin(e4c, e4d));
    enc = umin(enc, __shfl_xor_sync(gmask, enc, 1));
    enc = umin(enc, __shfl_xor_sync(gmask, enc, 2));

    // --- pairwise sum of exps ---
    float s8[8];
#pragma unroll
    for (int i = 0; i < 8; i++) s8[i] = v[2 * i] + v[2 * i + 1];
    float s4a = s8[0] + s8[1], s4b = s8[2] + s8[3];
    float s4c = s8[4] + s8[5], s4d = s8[6] + s8[7];
    float ssum = (s4a + s4b) + (s4c + s4d);
    ssum += __shfl_xor_sync(gmask, ssum, 1);
    ssum += __shfl_xor_sync(gmask, ssum, 2);

    const float inv = rcpf(ssum);
#pragma unroll
    for (int k = 0; k < 16; k++)
        acc[k] = fmaf(v[k], inv, acc[k]);

    // hard quantize (straight-through forward value = argmax codeword)
    if (lane_in_grp == 0)
        oq[n] = s_emb[enc];
}

__global__ __launch_bounds__(NTHREADS, BPS)
void jsccq_main(const float* __restrict__ x, const float* __restrict__ embed,
                float* __restrict__ out_q, float* __restrict__ out_like,
                int npts, float invN) {
    __shared__ float  s_cx[N_EMBED], s_cy[N_EMBED], s_cz[N_EMBED];
    __shared__ float2 s_emb[N_EMBED];
    __shared__ float  s_like[N_EMBED];
    __shared__ unsigned s_isLast;

    const int tid = threadIdx.x;
    if (tid < N_EMBED) {
        const float s = 10.0f * 1.4426950408889634f;   // sigma * log2(e)
        float ex = embed[2 * tid + 0];
        float ey = embed[2 * tid + 1];
        s_cx[tid]  = 2.0f * s * ex;
        s_cy[tid]  = 2.0f * s * ey;
        s_cz[tid]  = -s * (ex * ex + ey * ey);
        s_emb[tid]  = make_float2(ex, ey);
        s_like[tid] = 0.0f;
    }
    __syncthreads();

    const int lane_in_grp = tid & 3;
    const int base = lane_in_grp * 16;
    const unsigned gmask = 0xFu << ((tid & 31) & ~3);   // 4-lane group mask

    // Packed register-resident codebook slice (48 regs).
    u64 CX[8], CY[8], CZ[8];
#pragma unroll
    for (int i = 0; i < 8; i++) {
        CX[i] = pk2(s_cx[base + 2 * i], s_cx[base + 2 * i + 1]);
        CY[i] = pk2(s_cy[base + 2 * i], s_cy[base + 2 * i + 1]);
        CZ[i] = pk2(s_cz[base + 2 * i], s_cz[base + 2 * i + 1]);
    }

    float acc[16];
#pragma unroll
    for (int k = 0; k < 16; k++) acc[k] = 0.0f;

    const float2* __restrict__ pts = reinterpret_cast<const float2*>(x);
    float2* __restrict__       oq  = reinterpret_cast<float2*>(out_q);

    const int gid   = (blockIdx.x * NTHREADS + tid) >> 2;
    const int full2 = npts / (2 * NGROUPS);   // unguarded double-iterations

    int n = gid;
    float2 pA = pts[n];
    float2 pB = pts[n + NGROUPS];

    for (int it = 0; it < full2; it++) {
        const int nA = n, nB = n + NGROUPS;
        n += 2 * NGROUPS;
        // prefetch next pair (guard only near the end)
        float2 qA = (n < npts) ? pts[n] : make_float2(0.0f, 0.0f);
        float2 qB = (n + NGROUPS < npts) ? pts[n + NGROUPS] : make_float2(0.0f, 0.0f);

        // two independent bodies -> their SHFL/MUFU chains interleave
        point_body(pA, nA, base, lane_in_grp, gmask, CX, CY, CZ, acc, s_emb, oq);
        point_body(pB, nB, base, lane_in_grp, gmask, CX, CY, CZ, acc, s_emb, oq);

        pA = qA;
        pB = qB;
    }
    // guarded tail: up to 2 points per group (group-uniform branches)
    if (n < npts)
        point_body(pA, n, base, lane_in_grp, gmask, CX, CY, CZ, acc, s_emb, oq);
    if (n + NGROUPS < npts)
        point_body(pB, n + NGROUPS, base, lane_in_grp, gmask, CX, CY, CZ, acc, s_emb, oq);

    // --- block-level likelihood reduction (3 warps) ---
#pragma unroll
    for (int k = 0; k < 16; k++) {
        float vv = acc[k];
        vv += __shfl_xor_sync(0xffffffffu, vv, 4);
        vv += __shfl_xor_sync(0xffffffffu, vv, 8);
        vv += __shfl_xor_sync(0xffffffffu, vv, 16);
        if ((tid & 31) < 4)
            atomicAdd(&s_like[base + k], vv);
    }
    __syncthreads();
    if (tid < N_EMBED)
        g_part[tid * NBLK + blockIdx.x] = s_like[tid];
    __threadfence();
    __syncthreads();

    // --- last-arriving block reduces partials (replay-safe via mod) ---
    if (tid == 0) {
        unsigned t = atomicAdd(&g_tick, 1u);
        s_isLast = ((t % NBLK) == (NBLK - 1)) ? 1u : 0u;
    }
    __syncthreads();

    if (s_isLast && out_like != nullptr) {
        __threadfence();
        if (tid < N_EMBED) {
            const float4* row = reinterpret_cast<const float4*>(&g_part[tid * NBLK]);
            float s = 0.0f;
#pragma unroll 5
            for (int i = 0; i < NBLK / 4; i++) {
                float4 q = row[i];
                s += (q.x + q.y) + (q.z + q.w);
            }
            out_like[tid] = s * invN;
        }
    }
}

extern "C" void kernel_launch(void* const* d_in, const int* in_sizes, int n_in,
                              void* d_out, int out_size) {
    const float* x     = (const float*)d_in[0];   // [64,32,32,32] fp32
    const float* embed = (const float*)d_in[1];   // [64,2]        fp32
    float* out = (float*)d_out;

    const int npts = in_sizes[0] / 2;             // 1,048,576 points

    float* out_like = (out_size >= 2 * npts + N_EMBED) ? (out + 2 * npts) : nullptr;

    jsccq_main<<<NBLK, NTHREADS>>>(x, embed, out, out_like, npts,
                                   1.0f / (float)npts);
}

// round 14
// speedup vs baseline: 1.2337x; 1.2302x over previous
#include <cuda_runtime.h>

#define N_EMBED   64
#define BPS       3
#define NSM       152
#define NBLK      (NSM * BPS)              // 456
#define NTHREADS  128
#define NGROUPS   (NBLK * NTHREADS / 4)    // 14592 four-lane groups

// Per-block likelihood partials [codeword][block] + launch-persistent ticket.
__device__ __align__(16) float g_part[N_EMBED * NBLK];
__device__ unsigned int g_tick;

__device__ __forceinline__ float ex2f(float x) { float r; asm("ex2.approx.f32 %0,%1;" : "=f"(r) : "f"(x)); return r; }
__device__ __forceinline__ float rcpf(float x) { float r; asm("rcp.approx.f32 %0,%1;" : "=f"(r) : "f"(x)); return r; }

// One point's full pipeline for this lane's 16 codewords. Scalar ops only:
// FFMA/FADD on fma pipe, FMNMX/IMNMX/LOP on alu, EX2/RCP on MUFU — zero
// pack/unpack MOV traffic. EXACT max + EXACT argmax (umin over bits(d)|idx).
__device__ __forceinline__ void point_body(
    float2 p, int n, int base, int lane_in_grp, unsigned gmask,
    const float cx[16], const float cy[16], const float cz[16],
    float acc[16], const float2* __restrict__ s_emb,
    float2* __restrict__ oq)
{
    // --- logits: l[k] = px*cx + py*cy + cz ---
    float l[16];
#pragma unroll
    for (int k = 0; k < 16; k++)
        l[k] = fmaf(p.x, cx[k], fmaf(p.y, cy[k], cz[k]));

    // --- exact max: FMNMX tree + 2-level cross-lane ---
    float m8[8];
#pragma unroll
    for (int i = 0; i < 8; i++) m8[i] = fmaxf(l[2 * i], l[2 * i + 1]);
    float m4a = fmaxf(m8[0], m8[1]), m4b = fmaxf(m8[2], m8[3]);
    float m4c = fmaxf(m8[4], m8[5]), m4d = fmaxf(m8[6], m8[7]);
    float m   = fmaxf(fmaxf(m4a, m4b), fmaxf(m4c, m4d));
    m = fmaxf(m, __shfl_xor_sync(gmask, m, 1));
    m = fmaxf(m, __shfl_xor_sync(gmask, m, 2));

    // --- fused shift -> (argmax encode, exp) per pair ---
    // d = l - m <= 0, d == +0 exactly at the max; umin over (bits(d)|idx):
    // negatives carry the sign bit and lose; ties pick the smallest index
    // (matches jnp.argmax first-occurrence). Exact.
    float v[16];
    unsigned e8[8];
#pragma unroll
    for (int i = 0; i < 8; i++) {
        float d0 = l[2 * i]     - m;
        float d1 = l[2 * i + 1] - m;
        e8[i] = umin(__float_as_uint(d0) | (unsigned)(base + 2 * i),
                     __float_as_uint(d1) | (unsigned)(base + 2 * i + 1));
        v[2 * i]     = ex2f(d0);
        v[2 * i + 1] = ex2f(d1);
    }

    unsigned e4a = umin(e8[0], e8[1]), e4b = umin(e8[2], e8[3]);
    unsigned e4c = umin(e8[4], e8[5]), e4d = umin(e8[6], e8[7]);
    unsigned enc = umin(umin(e4a, e4b), umin(e4c, e4d));
    enc = umin(enc, __shfl_xor_sync(gmask, enc, 1));
    enc = umin(enc, __shfl_xor_sync(gmask, enc, 2));

    // --- pairwise sum of exps ---
    float s8[8];
#pragma unroll
    for (int i = 0; i < 8; i++) s8[i] = v[2 * i] + v[2 * i + 1];
    float s4a = s8[0] + s8[1], s4b = s8[2] + s8[3];
    float s4c = s8[4] + s8[5], s4d = s8[6] + s8[7];
    float ssum = (s4a + s4b) + (s4c + s4d);
    ssum += __shfl_xor_sync(gmask, ssum, 1);
    ssum += __shfl_xor_sync(gmask, ssum, 2);

    const float inv = rcpf(ssum);
#pragma unroll
    for (int k = 0; k < 16; k++)
        acc[k] = fmaf(v[k], inv, acc[k]);

    // hard quantize (straight-through forward value = argmax codeword)
    if (lane_in_grp == 0)
        oq[n] = s_emb[enc];
}

__global__ __launch_bounds__(NTHREADS, BPS)
void jsccq_main(const float* __restrict__ x, const float* __restrict__ embed,
                float* __restrict__ out_q, float* __restrict__ out_like,
                int npts, float invN) {
    __shared__ float  s_cx[N_EMBED], s_cy[N_EMBED], s_cz[N_EMBED];
    __shared__ float2 s_emb[N_EMBED];
    __shared__ float  s_like[N_EMBED];
    __shared__ unsigned s_isLast;

    const int tid = threadIdx.x;
    if (tid < N_EMBED) {
        const float s = 10.0f * 1.4426950408889634f;   // sigma * log2(e)
        float ex = embed[2 * tid + 0];
        float ey = embed[2 * tid + 1];
        s_cx[tid]  = 2.0f * s * ex;
        s_cy[tid]  = 2.0f * s * ey;
        s_cz[tid]  = -s * (ex * ex + ey * ey);
        s_emb[tid]  = make_float2(ex, ey);
        s_like[tid] = 0.0f;
    }
    __syncthreads();

    const int lane_in_grp = tid & 3;
    const int base = lane_in_grp * 16;
    const unsigned gmask = 0xFu << ((tid & 31) & ~3);   // 4-lane group mask

    // Register-resident codebook slice (48 regs).
    float cx[16], cy[16], cz[16];
#pragma unroll
    for (int k = 0; k < 16; k++) {
        cx[k] = s_cx[base + k];
        cy[k] = s_cy[base + k];
        cz[k] = s_cz[base + k];
    }

    float acc[16];
#pragma unroll
    for (int k = 0; k < 16; k++) acc[k] = 0.0f;

    const float2* __restrict__ pts = reinterpret_cast<const float2*>(x);
    float2* __restrict__       oq  = reinterpret_cast<float2*>(out_q);

    const int gid   = (blockIdx.x * NTHREADS + tid) >> 2;
    const int full2 = npts / (2 * NGROUPS);   // unguarded double-iterations

    int n = gid;
    float2 pA = pts[n];
    float2 pB = pts[n + NGROUPS];

    for (int it = 0; it < full2; it++) {
        const int nA = n, nB = n + NGROUPS;
        n += 2 * NGROUPS;
        // prefetch next pair (guard only near the end)
        float2 qA = (n < npts) ? pts[n] : make_float2(0.0f, 0.0f);
        float2 qB = (n + NGROUPS < npts) ? pts[n + NGROUPS] : make_float2(0.0f, 0.0f);

        // two independent bodies -> their SHFL/MUFU chains interleave
        point_body(pA, nA, base, lane_in_grp, gmask, cx, cy, cz, acc, s_emb, oq);
        point_body(pB, nB, base, lane_in_grp, gmask, cx, cy, cz, acc, s_emb, oq);

        pA = qA;
        pB = qB;
    }
    // guarded tail: up to 2 points per group (group-uniform branches)
    if (n < npts)
        point_body(pA, n, base, lane_in_grp, gmask, cx, cy, cz, acc, s_emb, oq);
    if (n + NGROUPS < npts)
        point_body(pB, n + NGROUPS, base, lane_in_grp, gmask, cx, cy, cz, acc, s_emb, oq);

    // --- block-level likelihood reduction ---
#pragma unroll
    for (int k = 0; k < 16; k++) {
        float vv = acc[k];
        vv += __shfl_xor_sync(0xffffffffu, vv, 4);
        vv += __shfl_xor_sync(0xffffffffu, vv, 8);
        vv += __shfl_xor_sync(0xffffffffu, vv, 16);
        if ((tid & 31) < 4)
            atomicAdd(&s_like[base + k], vv);
    }
    __syncthreads();
    if (tid < N_EMBED)
        g_part[tid * NBLK + blockIdx.x] = s_like[tid];
    __threadfence();
    __syncthreads();

    // --- last-arriving block reduces partials (replay-safe via mod) ---
    if (tid == 0) {
        unsigned t = atomicAdd(&g_tick, 1u);
        s_isLast = ((t % NBLK) == (NBLK - 1)) ? 1u : 0u;
    }
    __syncthreads();

    if (s_isLast && out_like != nullptr) {
        __threadfence();
        const int cw = tid >> 1;                     // 2 threads per codeword
        const float4* row = reinterpret_cast<const float4*>(&g_part[cw * NBLK])
                          + (tid & 1) * (NBLK / 8);  // 57 float4 each
        float s = 0.0f;
#pragma unroll 3
        for (int i = 0; i < NBLK / 8; i++) {
            float4 q = row[i];
            s += (q.x + q.y) + (q.z + q.w);
        }
        s += __shfl_xor_sync(0xffffffffu, s, 1);
        if ((tid & 1) == 0)
            out_like[cw] = s * invN;
    }
}

extern "C" void kernel_launch(void* const* d_in, const int* in_sizes, int n_in,
                              void* d_out, int out_size) {
    const float* x     = (const float*)d_in[0];   // [64,32,32,32] fp32
    const float* embed = (const float*)d_in[1];   // [64,2]        fp32
    float* out = (float*)d_out;

    const int npts = in_sizes[0] / 2;             // 1,048,576 points

    float* out_like = (out_size >= 2 * npts + N_EMBED) ? (out + 2 * npts) : nullptr;

    jsccq_main<<<NBLK, NTHREADS>>>(x, embed, out, out_like, npts,
                                   1.0f / (float)npts);
}

// round 15
// speedup vs baseline: 1.3051x; 1.0579x over previous
#include <cuda_runtime.h>

#define N_EMBED   64
#define BPS       3
#define NSM       152
#define NBLK      (NSM * BPS)              // 456
#define NTHREADS  128
#define NGROUPS   (NBLK * NTHREADS / 4)    // 14592 four-lane groups

typedef unsigned long long u64;

// Per-block likelihood partials [codeword][block] + launch-persistent ticket.
__device__ __align__(16) float g_part[N_EMBED * NBLK];
__device__ unsigned int g_tick;

__device__ __forceinline__ float ex2f(float x) { float r; asm("ex2.approx.f32 %0,%1;" : "=f"(r) : "f"(x)); return r; }
__device__ __forceinline__ float rcpf(float x) { float r; asm("rcp.approx.f32 %0,%1;" : "=f"(r) : "f"(x)); return r; }
__device__ __forceinline__ u64  pk2(float lo, float hi) { u64 r; asm("mov.b64 %0,{%1,%2};" : "=l"(r) : "f"(lo), "f"(hi)); return r; }
__device__ __forceinline__ void up2(u64 v, float& lo, float& hi) { asm("mov.b64 {%0,%1},%2;" : "=f"(lo), "=f"(hi) : "l"(v)); }
__device__ __forceinline__ u64  ffma2(u64 a, u64 b, u64 c) { u64 d; asm("fma.rn.f32x2 %0,%1,%2,%3;" : "=l"(d) : "l"(a), "l"(b), "l"(c)); return d; }
__device__ __forceinline__ u64  add2(u64 a, u64 b) { u64 d; asm("add.rn.f32x2 %0,%1,%2;" : "=l"(d) : "l"(a), "l"(b)); return d; }

// One point's full pipeline for this lane's 16 codewords (constants packed).
// EXACT max (FMNMX tree) + EXACT argmax (umin over bits(d)|idx; d == +0 only
// at the max, ties -> smallest index = jnp first-occurrence). The shifted
// pair is consumed immediately (encode + EX2) to minimize the live set.
__device__ __forceinline__ void point_body(
    float2 p, int n, int base, int lane_in_grp, unsigned gmask,
    const u64 CX[8], const u64 CY[8], const u64 CZ[8],
    float acc[16], const float2* __restrict__ s_emb,
    float2* __restrict__ oq)
{
    const u64 PX = pk2(p.x, p.x);
    const u64 PY = pk2(p.y, p.y);

    // --- logits (packed FFMA2): l[k] = px*cx + py*cy + cz ---
    u64 L[8];
    float l[16];
#pragma unroll
    for (int i = 0; i < 8; i++) {
        L[i] = ffma2(PX, CX[i], ffma2(PY, CY[i], CZ[i]));
        up2(L[i], l[2 * i], l[2 * i + 1]);
    }

    // --- exact max: FMNMX tree + 2-level cross-lane ---
    float m8[8];
#pragma unroll
    for (int i = 0; i < 8; i++) m8[i] = fmaxf(l[2 * i], l[2 * i + 1]);
    float m4a = fmaxf(m8[0], m8[1]), m4b = fmaxf(m8[2], m8[3]);
    float m4c = fmaxf(m8[4], m8[5]), m4d = fmaxf(m8[6], m8[7]);
    float m   = fmaxf(fmaxf(m4a, m4b), fmaxf(m4c, m4d));
    m = fmaxf(m, __shfl_xor_sync(gmask, m, 1));
    m = fmaxf(m, __shfl_xor_sync(gmask, m, 2));

    // --- fused shift (packed ADD2) -> (argmax encode, exp) per pair ---
    const u64 MM = pk2(-m, -m);
    float v[16];
    unsigned e8[8];
#pragma unroll
    for (int i = 0; i < 8; i++) {
        float d0, d1;
        up2(add2(L[i], MM), d0, d1);
        e8[i] = umin(__float_as_uint(d0) | (unsigned)(base + 2 * i),
                     __float_as_uint(d1) | (unsigned)(base + 2 * i + 1));
        v[2 * i]     = ex2f(d0);
        v[2 * i + 1] = ex2f(d1);
    }

    unsigned e4a = umin(e8[0], e8[1]), e4b = umin(e8[2], e8[3]);
    unsigned e4c = umin(e8[4], e8[5]), e4d = umin(e8[6], e8[7]);
    unsigned enc = umin(umin(e4a, e4b), umin(e4c, e4d));
    enc = umin(enc, __shfl_xor_sync(gmask, enc, 1));
    enc = umin(enc, __shfl_xor_sync(gmask, enc, 2));

    // --- pairwise sum of exps ---
    float s8[8];
#pragma unroll
    for (int i = 0; i < 8; i++) s8[i] = v[2 * i] + v[2 * i + 1];
    float s4a = s8[0] + s8[1], s4b = s8[2] + s8[3];
    float s4c = s8[4] + s8[5], s4d = s8[6] + s8[7];
    float ssum = (s4a + s4b) + (s4c + s4d);
    ssum += __shfl_xor_sync(gmask, ssum, 1);
    ssum += __shfl_xor_sync(gmask, ssum, 2);

    const float inv = rcpf(ssum);
#pragma unroll
    for (int k = 0; k < 16; k++)
        acc[k] = fmaf(v[k], inv, acc[k]);

    // hard quantize (straight-through forward value = argmax codeword)
    if (lane_in_grp == 0)
        oq[n] = s_emb[enc];
}

__global__ __launch_bounds__(NTHREADS, BPS)
void jsccq_main(const float* __restrict__ x, const float* __restrict__ embed,
                float* __restrict__ out_q, float* __restrict__ out_like,
                int npts, float invN) {
    __shared__ float  s_cx[N_EMBED], s_cy[N_EMBED], s_cz[N_EMBED];
    __shared__ float2 s_emb[N_EMBED];
    __shared__ float  s_like[N_EMBED];
    __shared__ unsigned s_isLast;

    const int tid = threadIdx.x;
    if (tid < N_EMBED) {
        const float s = 10.0f * 1.4426950408889634f;   // sigma * log2(e)
        float ex = embed[2 * tid + 0];
        float ey = embed[2 * tid + 1];
        s_cx[tid]  = 2.0f * s * ex;
        s_cy[tid]  = 2.0f * s * ey;
        s_cz[tid]  = -s * (ex * ex + ey * ey);
        s_emb[tid]  = make_float2(ex, ey);
        s_like[tid] = 0.0f;
    }
    __syncthreads();

    const int lane_in_grp = tid & 3;
    const int base = lane_in_grp * 16;
    const unsigned gmask = 0xFu << ((tid & 31) & ~3);   // 4-lane group mask

    // Packed register-resident codebook slice (48 regs).
    u64 CX[8], CY[8], CZ[8];
#pragma unroll
    for (int i = 0; i < 8; i++) {
        CX[i] = pk2(s_cx[base + 2 * i], s_cx[base + 2 * i + 1]);
        CY[i] = pk2(s_cy[base + 2 * i], s_cy[base + 2 * i + 1]);
        CZ[i] = pk2(s_cz[base + 2 * i], s_cz[base + 2 * i + 1]);
    }

    float acc[16];
#pragma unroll
    for (int k = 0; k < 16; k++) acc[k] = 0.0f;

    const float2* __restrict__ pts = reinterpret_cast<const float2*>(x);
    float2* __restrict__       oq  = reinterpret_cast<float2*>(out_q);

    const int gid   = (blockIdx.x * NTHREADS + tid) >> 2;
    const int full3 = npts / (3 * NGROUPS);   // unguarded triple-iterations

    int n = gid;
    float2 pA = pts[n];
    float2 pB = pts[n + NGROUPS];
    float2 pC = pts[n + 2 * NGROUPS];

    for (int it = 0; it < full3; it++) {
        const int nA = n, nB = n + NGROUPS, nC = n + 2 * NGROUPS;
        n += 3 * NGROUPS;
        // prefetch next triple (guard only near the end)
        float2 qA = (n < npts)               ? pts[n]               : make_float2(0.0f, 0.0f);
        float2 qB = (n + NGROUPS < npts)     ? pts[n + NGROUPS]     : make_float2(0.0f, 0.0f);
        float2 qC = (n + 2 * NGROUPS < npts) ? pts[n + 2 * NGROUPS] : make_float2(0.0f, 0.0f);

        // three independent bodies -> three SHFL/MUFU chains interleave
        point_body(pA, nA, base, lane_in_grp, gmask, CX, CY, CZ, acc, s_emb, oq);
        point_body(pB, nB, base, lane_in_grp, gmask, CX, CY, CZ, acc, s_emb, oq);
        point_body(pC, nC, base, lane_in_grp, gmask, CX, CY, CZ, acc, s_emb, oq);

        pA = qA; pB = qB; pC = qC;
    }
    // guarded tail: up to 3 points per group (group-uniform branches)
    if (n < npts)
        point_body(pA, n, base, lane_in_grp, gmask, CX, CY, CZ, acc, s_emb, oq);
    if (n + NGROUPS < npts)
        point_body(pB, n + NGROUPS, base, lane_in_grp, gmask, CX, CY, CZ, acc, s_emb, oq);
    if (n + 2 * NGROUPS < npts)
        point_body(pC, n + 2 * NGROUPS, base, lane_in_grp, gmask, CX, CY, CZ, acc, s_emb, oq);

    // --- block-level likelihood reduction ---
#pragma unroll
    for (int k = 0; k < 16; k++) {
        float vv = acc[k];
        vv += __shfl_xor_sync(0xffffffffu, vv, 4);
        vv += __shfl_xor_sync(0xffffffffu, vv, 8);
        vv += __shfl_xor_sync(0xffffffffu, vv, 16);
        if ((tid & 31) < 4)
            atomicAdd(&s_like[base + k], vv);
    }
    __syncthreads();
    if (tid < N_EMBED)
        g_part[tid * NBLK + blockIdx.x] = s_like[tid];
    __threadfence();
    __syncthreads();

    // --- last-arriving block reduces partials (replay-safe via mod) ---
    if (tid == 0) {
        unsigned t = atomicAdd(&g_tick, 1u);
        s_isLast = ((t % NBLK) == (NBLK - 1)) ? 1u : 0u;
    }
    __syncthreads();

    if (s_isLast && out_like != nullptr) {
        __threadfence();
        const int cw = tid >> 1;                     // 2 threads per codeword
        const float4* row = reinterpret_cast<const float4*>(&g_part[cw * NBLK])
                          + (tid & 1) * (NBLK / 8);  // 57 float4 each
        float s = 0.0f;
#pragma unroll 3
        for (int i = 0; i < NBLK / 8; i++) {
            float4 q = row[i];
            s += (q.x + q.y) + (q.z + q.w);
        }
        s += __shfl_xor_sync(0xffffffffu, s, 1);
        if ((tid & 1) == 0)
            out_like[cw] = s * invN;
    }
}

extern "C" void kernel_launch(void* const* d_in, const int* in_sizes, int n_in,
                              void* d_out, int out_size) {
    const float* x     = (const float*)d_in[0];   // [64,32,32,32] fp32
    const float* embed = (const float*)d_in[1];   // [64,2]        fp32
    float* out = (float*)d_out;

    const int npts = in_sizes[0] / 2;             // 1,048,576 points

    float* out_like = (out_size >= 2 * npts + N_EMBED) ? (out + 2 * npts) : nullptr;

    jsccq_main<<<NBLK, NTHREADS>>>(x, embed, out, out_like, npts,
                                   1.0f / (float)npts);
}